// round 5
// baseline (speedup 1.0000x reference)
#include <cuda_runtime.h>
#include <cuda_bf16.h>

// ShiftImgPreprocessor: out[b,t,c,i,j] = img[b,t,c, clamp(i+sy-PAD,0,H-1),
//                                              clamp(j+sx-PAD,0,W-1)] / 255 - 0.5
// img (256,4,3,96,96) fp32, shift (256,2) int32 (sx=shift[b][0], sy=shift[b][1]).
//
// R5: R4 + deeper MLP. Each warp handles 8 consecutive rows of ONE plane
// (96%8==0), so b/sx/sy/x-clamps are computed once per warp and each lane
// front-batches 24 independent scalar loads before any store. Stores stay
// aligned warp-contiguous STG.32.

#define PAD 4
#define N_IMG 256
#define T_IMG 4
#define C_IMG 3
#define H_IMG 96
#define W_IMG 96
#define TC (T_IMG * C_IMG)                    // 12 planes per batch
#define N_PLANES (N_IMG * TC)                 // 3072
#define ROWS_PER_WARP 8
#define WARPS_PER_BLOCK 8
#define THREADS (WARPS_PER_BLOCK * 32)
#define ROWS_PER_BLOCK (WARPS_PER_BLOCK * ROWS_PER_WARP)   // 64
#define TOTAL_ROWS (N_PLANES * H_IMG)         // 294912
#define NBLOCKS (TOTAL_ROWS / ROWS_PER_BLOCK) // 4608

__global__ __launch_bounds__(THREADS) void shift_img_kernel(
    const float* __restrict__ img,
    const int*   __restrict__ shift,
    float*       __restrict__ out)
{
    const int warp = threadIdx.x >> 5;
    const int lane = threadIdx.x & 31;
    const int base = blockIdx.x * ROWS_PER_BLOCK + warp * ROWS_PER_WARP; // first row

    const float INV255 = 1.0f / 255.0f;

    const int plane = base / H_IMG;          // flattened (b,t,c); same for all 8 rows
    const int i0    = base % H_IMG;
    const int b     = plane / TC;

    const int sx = __ldg(&shift[2 * b + 0]);
    const int sy = __ldg(&shift[2 * b + 1]);
    const int d  = sx - PAD;                 // in [-4, 4]

    // x source columns, shared by all rows (computed once per warp)
    const int x0 = min(max(lane +  0 + d, 0), W_IMG - 1);
    const int x1 = min(max(lane + 32 + d, 0), W_IMG - 1);
    const int x2 = min(max(lane + 64 + d, 0), W_IMG - 1);

    const float* sp = img + (size_t)plane * (H_IMG * W_IMG);
    float*       dp = out + (size_t)base  * W_IMG;

    // ---- front-batch all 24 independent loads (deep MLP) ----
    float v[ROWS_PER_WARP][3];
    #pragma unroll
    for (int k = 0; k < ROWS_PER_WARP; k++) {
        const int sY = min(max(i0 + k + sy - PAD, 0), H_IMG - 1);
        const float* r = sp + sY * W_IMG;
        v[k][0] = __ldg(r + x0);
        v[k][1] = __ldg(r + x1);
        v[k][2] = __ldg(r + x2);
    }

    // ---- normalize + aligned contiguous stores ----
    #pragma unroll
    for (int k = 0; k < ROWS_PER_WARP; k++) {
        float* w = dp + k * W_IMG;
        w[lane +  0] = fmaf(v[k][0], INV255, -0.5f);
        w[lane + 32] = fmaf(v[k][1], INV255, -0.5f);
        w[lane + 64] = fmaf(v[k][2], INV255, -0.5f);
    }
}

extern "C" void kernel_launch(void* const* d_in, const int* in_sizes, int n_in,
                              void* d_out, int out_size)
{
    const float* img   = (const float*)d_in[0];
    const int*   shift = (const int*)d_in[1];
    float*       out   = (float*)d_out;

    shift_img_kernel<<<NBLOCKS, THREADS>>>(img, shift, out);
}

// round 8
// speedup vs baseline: 1.0140x; 1.0140x over previous
#include <cuda_runtime.h>
#include <cuda_bf16.h>

// ShiftImgPreprocessor: out[b,t,c,i,j] = img[b,t,c, clamp(i+sy-PAD,0,H-1),
//                                              clamp(j+sx-PAD,0,W-1)] / 255 - 0.5
// img (256,4,3,96,96) fp32, shift (256,2) int32 (sx=shift[b][0], sy=shift[b][1]).
//
// R7: R4 structure (4 rows/warp, warp-contiguous, front-batched MLP) + L2
// cache-policy descriptors. sm_103a ptxas rejects scalar ld with inline
// .L2::evict_last; the descriptor form (createpolicy + .L2::cache_hint) is the
// supported scalar path. Input (113MB, ~fits 126MB L2) gets evict_last so it
// stays resident across graph replays; output stores get evict_first/.cs so
// the dirty write stream doesn't evict it.

#define PAD 4
#define N_IMG 256
#define T_IMG 4
#define C_IMG 3
#define H_IMG 96
#define W_IMG 96
#define TC (T_IMG * C_IMG)                    // 12 planes per batch
#define N_PLANES (N_IMG * TC)                 // 3072
#define ROWS_PER_WARP 4
#define WARPS_PER_BLOCK 8
#define THREADS (WARPS_PER_BLOCK * 32)
#define ROWS_PER_BLOCK (WARPS_PER_BLOCK * ROWS_PER_WARP)   // 32
#define TOTAL_ROWS (N_PLANES * H_IMG)         // 294912
#define NBLOCKS (TOTAL_ROWS / ROWS_PER_BLOCK) // 9216

__device__ __forceinline__ unsigned long long policy_evict_last() {
    unsigned long long p;
    asm("createpolicy.fractional.L2::evict_last.b64 %0, 1.0;" : "=l"(p));
    return p;
}

__device__ __forceinline__ unsigned long long policy_evict_first() {
    unsigned long long p;
    asm("createpolicy.fractional.L2::evict_first.b64 %0, 1.0;" : "=l"(p));
    return p;
}

__device__ __forceinline__ float ldg_hint(const float* p, unsigned long long pol) {
    float v;
    asm volatile("ld.global.nc.L2::cache_hint.f32 %0, [%1], %2;"
                 : "=f"(v) : "l"(p), "l"(pol));
    return v;
}

__device__ __forceinline__ void stg_hint(float* p, float v, unsigned long long pol) {
    asm volatile("st.global.cs.L2::cache_hint.f32 [%0], %1, %2;"
                 :: "l"(p), "f"(v), "l"(pol));
}

__global__ __launch_bounds__(THREADS) void shift_img_kernel(
    const float* __restrict__ img,
    const int*   __restrict__ shift,
    float*       __restrict__ out)
{
    const int warp = threadIdx.x >> 5;
    const int lane = threadIdx.x & 31;
    const int base = blockIdx.x * ROWS_PER_BLOCK + warp * ROWS_PER_WARP; // first row

    const float INV255 = 1.0f / 255.0f;

    const unsigned long long pol_in  = policy_evict_last();
    const unsigned long long pol_out = policy_evict_first();

    const int plane = base / H_IMG;          // flattened (b,t,c); same for all 4 rows
    const int i0    = base % H_IMG;
    const int b     = plane / TC;

    const int sx = __ldg(&shift[2 * b + 0]);
    const int sy = __ldg(&shift[2 * b + 1]);
    const int d  = sx - PAD;                 // in [-4, 4]

    // x source columns, shared by all rows (computed once per warp)
    const int x0 = min(max(lane +  0 + d, 0), W_IMG - 1);
    const int x1 = min(max(lane + 32 + d, 0), W_IMG - 1);
    const int x2 = min(max(lane + 64 + d, 0), W_IMG - 1);

    const float* sp = img + (size_t)plane * (H_IMG * W_IMG);
    float*       dp = out + (size_t)base  * W_IMG;

    // ---- front-batch all 12 independent loads (deep MLP), input pinned in L2 ----
    float v[ROWS_PER_WARP][3];
    #pragma unroll
    for (int k = 0; k < ROWS_PER_WARP; k++) {
        const int sY = min(max(i0 + k + sy - PAD, 0), H_IMG - 1);
        const float* r = sp + sY * W_IMG;
        v[k][0] = ldg_hint(r + x0, pol_in);
        v[k][1] = ldg_hint(r + x1, pol_in);
        v[k][2] = ldg_hint(r + x2, pol_in);
    }

    // ---- normalize + aligned contiguous streaming stores ----
    #pragma unroll
    for (int k = 0; k < ROWS_PER_WARP; k++) {
        float* w = dp + k * W_IMG;
        stg_hint(w + lane +  0, fmaf(v[k][0], INV255, -0.5f), pol_out);
        stg_hint(w + lane + 32, fmaf(v[k][1], INV255, -0.5f), pol_out);
        stg_hint(w + lane + 64, fmaf(v[k][2], INV255, -0.5f), pol_out);
    }
}

extern "C" void kernel_launch(void* const* d_in, const int* in_sizes, int n_in,
                              void* d_out, int out_size)
{
    const float* img   = (const float*)d_in[0];
    const int*   shift = (const int*)d_in[1];
    float*       out   = (float*)d_out;

    shift_img_kernel<<<NBLOCKS, THREADS>>>(img, shift, out);
}